// round 2
// baseline (speedup 1.0000x reference)
#include <cuda_runtime.h>

#define LL 4096
#define CC 16
#define NB 16
#define OC 64
#define KS 7

__global__ __launch_bounds__(256) void deform_conv_kernel(
    const float* __restrict__ x,
    const float* __restrict__ pw, const float* __restrict__ pb,
    const float* __restrict__ mw, const float* __restrict__ mb,
    const float* __restrict__ cw, const float* __restrict__ cb,
    float* __restrict__ out)
{
    __shared__ float s_cw[OC][8];      // padded to 8 for float4 loads
    __shared__ float s_cb[OC];
    __shared__ float s_pw[KS * 3], s_pb[KS], s_mw[KS * 3], s_mb[KS];

    const int tid = threadIdx.x;
    for (int i = tid; i < OC * KS; i += blockDim.x)
        s_cw[i / KS][i % KS] = cw[i];
    if (tid < OC) s_cb[tid] = cb[tid];
    if (tid < KS * 3) { s_pw[tid] = pw[tid]; s_mw[tid] = mw[tid]; }
    if (tid < KS)     { s_pb[tid] = pb[tid]; s_mb[tid] = mb[tid]; }
    __syncthreads();

    const int t  = blockIdx.x * blockDim.x + tid;   // 2^18 threads total
    const int c4 = t & 3;                           // channel group (4 floats)
    const int l  = (t >> 2) & (LL - 1);
    const int b  = t >> 14;                         // 4*LL = 2^14 per batch

    const float* xb = x + (size_t)b * (LL * CC);
    const float4* xb4 = (const float4*)xb;

    // 3-tap window over 4 channels (zero padding at the edges, pad=1 conv)
    float4 sm1 = (l > 0)      ? xb4[(l - 1) * 4 + c4] : make_float4(0.f, 0.f, 0.f, 0.f);
    float4 s0  =                xb4[l * 4 + c4];
    float4 sp1 = (l < LL - 1) ? xb4[(l + 1) * 4 + c4] : make_float4(0.f, 0.f, 0.f, 0.f);

    float win[4][3] = {{sm1.x, s0.x, sp1.x}, {sm1.y, s0.y, sp1.y},
                       {sm1.z, s0.z, sp1.z}, {sm1.w, s0.w, sp1.w}};

    float v[4][KS];
    #pragma unroll
    for (int k = 0; k < KS; ++k) {
        const float w0 = s_pw[k * 3], w1 = s_pw[k * 3 + 1], w2 = s_pw[k * 3 + 2];
        const float u0 = s_mw[k * 3], u1 = s_mw[k * 3 + 1], u2 = s_mw[k * 3 + 2];
        const float bo = s_pb[k], bm = s_mb[k];
        const float pbase = (float)(l + 1 + (k - 3));   // p_0 is 1-indexed
        #pragma unroll
        for (int i = 0; i < 4; ++i) {
            float off = fmaf(w2, win[i][2], fmaf(w1, win[i][1], fmaf(w0, win[i][0], bo)));
            float z   = fmaf(u2, win[i][2], fmaf(u1, win[i][1], fmaf(u0, win[i][0], bm)));
            float m   = 1.f / (1.f + __expf(-z));       // sigmoid
            float p   = pbase + off;
            float qlt = fminf(fmaxf(floorf(p), 0.f), (float)(LL - 1));
            float qrb = fminf(qlt + 1.f, (float)(LL - 1));
            float pc  = fminf(fmaxf(p, 0.f), (float)(LL - 1));
            float glt = 1.f + (qlt - pc);
            float grb = 1.f - (qrb - pc);
            const int ch = c4 * 4 + i;
            float xlt = xb[(int)qlt * CC + ch];
            float xrb = xb[(int)qrb * CC + ch];
            v[i][k] = (glt * xlt + grb * xrb) * m;
        }
    }

    float4* out4 = (float4*)out;
    const float4* scw4 = (const float4*)s_cw;           // [64][2] float4 rows
    const int obase = (b * OC) * LL + l;                // float4 row index base

    #pragma unroll 4
    for (int oc = 0; oc < OC; ++oc) {
        float4 wlo = scw4[oc * 2];
        float4 whi = scw4[oc * 2 + 1];
        float wk[KS] = {wlo.x, wlo.y, wlo.z, wlo.w, whi.x, whi.y, whi.z};
        const float bias = s_cb[oc];
        float a0 = bias, a1 = bias, a2 = bias, a3 = bias;
        #pragma unroll
        for (int k = 0; k < KS; ++k) {
            a0 = fmaf(wk[k], v[0][k], a0);
            a1 = fmaf(wk[k], v[1][k], a1);
            a2 = fmaf(wk[k], v[2][k], a2);
            a3 = fmaf(wk[k], v[3][k], a3);
        }
        out4[(obase + oc * LL) * 4 + c4] = make_float4(a0, a1, a2, a3);
    }
}

extern "C" void kernel_launch(void* const* d_in, const int* in_sizes, int n_in,
                              void* d_out, int out_size)
{
    const float* x  = (const float*)d_in[0];
    const float* pw = (const float*)d_in[1];
    const float* pb = (const float*)d_in[2];
    const float* mw = (const float*)d_in[3];
    const float* mb = (const float*)d_in[4];
    const float* cw = (const float*)d_in[5];
    const float* cb = (const float*)d_in[6];
    float* out = (float*)d_out;

    // 16 batches * 4096 positions * 4 channel-groups = 262144 threads
    deform_conv_kernel<<<1024, 256>>>(x, pw, pb, mw, mb, cw, cb, out);
}

// round 3
// speedup vs baseline: 1.1525x; 1.1525x over previous
#include <cuda_runtime.h>

#define LL 4096
#define CC 16
#define NB 16
#define OC 64
#define KS 7

__global__ __launch_bounds__(256, 5) void deform_conv_kernel(
    const float* __restrict__ x,
    const float* __restrict__ pw, const float* __restrict__ pb,
    const float* __restrict__ mw, const float* __restrict__ mb,
    const float* __restrict__ cw, const float* __restrict__ cb,
    float* __restrict__ out)
{
    __shared__ float s_cw[OC][8];      // padded to 8 for float4 loads
    __shared__ float s_cb[OC];
    __shared__ float s_pw[KS * 3], s_pb[KS], s_mw[KS * 3], s_mb[KS];

    const int tid = threadIdx.x;
    for (int i = tid; i < OC * KS; i += blockDim.x)
        s_cw[i / KS][i % KS] = cw[i];
    if (tid < OC) s_cb[tid] = cb[tid];
    if (tid < KS * 3) { s_pw[tid] = pw[tid]; s_mw[tid] = mw[tid]; }
    if (tid < KS)     { s_pb[tid] = pb[tid]; s_mb[tid] = mb[tid]; }
    __syncthreads();

    const int t  = blockIdx.x * blockDim.x + tid;   // 2^19 threads total
    const int c2 = t & 7;                           // channel pair (2 floats)
    const int l  = (t >> 3) & (LL - 1);
    const int b  = t >> 15;                         // 8*LL = 2^15 per batch

    const float* xb = x + (size_t)b * (LL * CC);
    const float2* xb2 = (const float2*)xb;

    // 3-tap window over 2 channels (zero padding at the edges, pad=1 conv)
    float2 sm1 = (l > 0)      ? xb2[(l - 1) * 8 + c2] : make_float2(0.f, 0.f);
    float2 s0  =                xb2[l * 8 + c2];
    float2 sp1 = (l < LL - 1) ? xb2[(l + 1) * 8 + c2] : make_float2(0.f, 0.f);

    float win[2][3] = {{sm1.x, s0.x, sp1.x}, {sm1.y, s0.y, sp1.y}};

    float v[2][KS];
    #pragma unroll
    for (int k = 0; k < KS; ++k) {
        const float w0 = s_pw[k * 3], w1 = s_pw[k * 3 + 1], w2 = s_pw[k * 3 + 2];
        const float u0 = s_mw[k * 3], u1 = s_mw[k * 3 + 1], u2 = s_mw[k * 3 + 2];
        const float bo = s_pb[k], bm = s_mb[k];
        const float pbase = (float)(l + 1 + (k - 3));   // p_0 is 1-indexed
        #pragma unroll
        for (int i = 0; i < 2; ++i) {
            float off = fmaf(w2, win[i][2], fmaf(w1, win[i][1], fmaf(w0, win[i][0], bo)));
            float z   = fmaf(u2, win[i][2], fmaf(u1, win[i][1], fmaf(u0, win[i][0], bm)));
            float m   = 1.f / (1.f + __expf(-z));       // sigmoid
            float p   = pbase + off;
            float qlt = fminf(fmaxf(floorf(p), 0.f), (float)(LL - 1));
            float qrb = fminf(qlt + 1.f, (float)(LL - 1));
            float pc  = fminf(fmaxf(p, 0.f), (float)(LL - 1));
            float glt = 1.f + (qlt - pc);
            float grb = 1.f - (qrb - pc);
            const int ch = c2 * 2 + i;
            float xlt = xb[(int)qlt * CC + ch];
            float xrb = xb[(int)qrb * CC + ch];
            v[i][k] = (glt * xlt + grb * xrb) * m;
        }
    }

    const float4* scw4 = (const float4*)s_cw;           // [64][2] float4 rows
    // out element base for (b, oc=0, l, c2*2)
    float2* out2 = (float2*)out;
    const int obase = ((b * OC) * LL + l) * 8 + c2;     // float2 index

    #pragma unroll 8
    for (int oc = 0; oc < OC; ++oc) {
        float4 wlo = scw4[oc * 2];
        float4 whi = scw4[oc * 2 + 1];
        float wk[KS] = {wlo.x, wlo.y, wlo.z, wlo.w, whi.x, whi.y, whi.z};
        const float bias = s_cb[oc];
        float a0 = bias, a1 = bias;
        #pragma unroll
        for (int k = 0; k < KS; ++k) {
            a0 = fmaf(wk[k], v[0][k], a0);
            a1 = fmaf(wk[k], v[1][k], a1);
        }
        __stcs(&out2[obase + oc * (LL * 8)], make_float2(a0, a1));
    }
}

extern "C" void kernel_launch(void* const* d_in, const int* in_sizes, int n_in,
                              void* d_out, int out_size)
{
    const float* x  = (const float*)d_in[0];
    const float* pw = (const float*)d_in[1];
    const float* pb = (const float*)d_in[2];
    const float* mw = (const float*)d_in[3];
    const float* mb = (const float*)d_in[4];
    const float* cw = (const float*)d_in[5];
    const float* cb = (const float*)d_in[6];
    float* out = (float*)d_out;

    // 16 batches * 4096 positions * 8 channel-pairs = 524288 threads
    deform_conv_kernel<<<2048, 256>>>(x, pw, pb, mw, mb, cw, cb, out);
}